// round 2
// baseline (speedup 1.0000x reference)
#include <cuda_runtime.h>
#include <math.h>

#define BB 16
#define EE 4
#define DIMC 64
#define RR 32
#define HH 128
#define WW 128
#define HWPX (HH*WW)
#define FREQN 64
#define NPAIR (BB*EE)

// ---------------- scratch (device globals) ----------------
__device__ float d_pooled[BB][DIMC];
__device__ float d_gates[BB][EE];
__device__ float d_gatesum[BB];
__device__ int   d_topidx[BB][2];
__device__ float d_qc[EE][RR][DIMC];
__device__ float d_kvc[EE][2*RR][DIMC];
__device__ float d_qpre[NPAIR][RR][HWPX];
__device__ float d_kvpre[NPAIR][2*RR][HWPX];
__device__ float d_qb[NPAIR][RR][HWPX];
__device__ float d_kb[NPAIR][RR][HWPX];
__device__ float d_vb[NPAIR][RR][HWPX];
__device__ float d_gact[NPAIR][RR][HWPX];
__device__ float d_attb[NPAIR][RR][HWPX];

// ---------------- K0: pooled mean ----------------
__global__ void k_pool(const float* __restrict__ x) {
    int bc = blockIdx.x;
    const float* p = x + (size_t)bc * HWPX;
    float s = 0.f;
    for (int i = threadIdx.x; i < HWPX; i += 256) s += p[i];
    __shared__ float sm[256];
    sm[threadIdx.x] = s;
    __syncthreads();
    for (int o = 128; o > 0; o >>= 1) {
        if (threadIdx.x < o) sm[threadIdx.x] += sm[threadIdx.x + o];
        __syncthreads();
    }
    if (threadIdx.x == 0) d_pooled[bc / DIMC][bc % DIMC] = sm[0] * (1.f / (float)HWPX);
}

// ---------------- K1: gating ----------------
__global__ void k_gate(const float* __restrict__ freq_emb, const float* __restrict__ noise,
                       const float* __restrict__ gate_w, const float* __restrict__ fgw) {
    int b = threadIdx.x;
    if (b >= BB) return;
    float lg[EE];
    for (int e = 0; e < EE; e++) {
        float s = 0.f;
        for (int d = 0; d < DIMC; d++) s += d_pooled[b][d] * gate_w[e * DIMC + d];
        for (int f = 0; f < FREQN; f++) s += freq_emb[b * FREQN + f] * fgw[e * FREQN + f];
        lg[e] = s + noise[b * EE + e] * (1.0f / (float)EE);
    }
    float mx = lg[0];
    for (int e = 1; e < EE; e++) mx = fmaxf(mx, lg[e]);
    float se = 0.f, sc[EE];
    for (int e = 0; e < EE; e++) { sc[e] = expf(lg[e] - mx); se += sc[e]; }
    for (int e = 0; e < EE; e++) sc[e] /= se;
    int i1 = 0;
    for (int e = 1; e < EE; e++) if (sc[e] > sc[i1]) i1 = e;
    int i2 = -1;
    for (int e = 0; e < EE; e++) {
        if (e == i1) continue;
        if (i2 < 0 || sc[e] > sc[i2]) i2 = e;
    }
    for (int e = 0; e < EE; e++) d_gates[b][e] = (e == i1 || e == i2) ? sc[e] : 0.f;
    d_gatesum[b] = sc[i1] + sc[i2];
    d_topidx[b][0] = i1;
    d_topidx[b][1] = i2;
}

// ---------------- K2: compose q_w@p0, kv_w@p0 ----------------
__global__ void k_compose(const float* __restrict__ p0, const float* __restrict__ q_w,
                          const float* __restrict__ kv_w) {
    int e = blockIdx.x;
    __shared__ float sp0[RR][DIMC];
    for (int i = threadIdx.x; i < RR * DIMC; i += 256)
        sp0[i / DIMC][i % DIMC] = p0[e * RR * DIMC + i];
    __syncthreads();
    for (int i = threadIdx.x; i < RR * DIMC; i += 256) {
        int o = i / DIMC, d = i % DIMC;
        float s = 0.f;
        for (int c = 0; c < RR; c++) s += q_w[(e * RR + o) * RR + c] * sp0[c][d];
        d_qc[e][o][d] = s;
    }
    for (int i = threadIdx.x; i < 2 * RR * DIMC; i += 256) {
        int o = i / DIMC, d = i % DIMC;
        float s = 0.f;
        for (int c = 0; c < RR; c++) s += kv_w[(e * 2 * RR + o) * RR + c] * sp0[c][d];
        d_kvc[e][o][d] = s;
    }
}

// ---------------- K3: GEMM-tiled per-pixel matmuls ----------------
// 128-px tile per block; pass1: 96 outs (q 32 + kv 64) from x; pass2: 32 outs (silu gate) from shared.
#define PXT 128
#define XST 132   // smem row stride (floats)
__global__ __launch_bounds__(384) void k_pre(const float* __restrict__ x,
                                             const float* __restrict__ shin,
                                             const float* __restrict__ p1) {
    extern __shared__ float sm[];
    float* xs = sm;                 // [64][XST] input tile  xs[d][px]
    float* ws = sm + 64 * XST;      // [64][XST] weights k-major ws[d][o]
    int pair = blockIdx.y;
    int b = pair / EE, e = pair % EE;
    if (d_gates[b][e] == 0.f) return;
    int t = threadIdx.x;
    int pbase = blockIdx.x * PXT;

    // load weights transposed (96 outs)
    for (int i = t; i < 96 * DIMC; i += 384) {
        int o = i / DIMC, d = i % DIMC;
        ws[d * XST + o] = (o < RR) ? d_qc[e][o][d] : d_kvc[e][o - RR][d];
    }
    // load x tile
    for (int i = t; i < 64 * (PXT / 4); i += 384) {
        int d = i / (PXT / 4), p4 = i % (PXT / 4);
        *(float4*)&xs[d * XST + p4 * 4] =
            *(const float4*)&x[((size_t)b * DIMC + d) * HWPX + pbase + p4 * 4];
    }
    __syncthreads();

    // pass1: 12 out-groups x 32 px-groups = 384 threads; 8 outs x 4 px per thread
    {
        int og = t % 12, pg = t / 12;
        int o0 = og * 8, p0 = pg * 4;
        float acc[8][4];
#pragma unroll
        for (int i = 0; i < 8; i++)
#pragma unroll
            for (int j = 0; j < 4; j++) acc[i][j] = 0.f;
#pragma unroll 4
        for (int d = 0; d < DIMC; d++) {
            const float* wr = ws + d * XST + o0;
            float4 w0 = *(const float4*)wr;
            float4 w1 = *(const float4*)(wr + 4);
            float4 xv = *(const float4*)(xs + d * XST + p0);
            float wv[8] = {w0.x, w0.y, w0.z, w0.w, w1.x, w1.y, w1.z, w1.w};
            float xr[4] = {xv.x, xv.y, xv.z, xv.w};
#pragma unroll
            for (int i = 0; i < 8; i++)
#pragma unroll
                for (int j = 0; j < 4; j++) acc[i][j] += wv[i] * xr[j];
        }
#pragma unroll
        for (int i = 0; i < 8; i++) {
            int o = o0 + i;
            float* dst = (o < RR) ? &d_qpre[pair][o][0] : &d_kvpre[pair][o - RR][0];
            *(float4*)&dst[pbase + p0] = make_float4(acc[i][0], acc[i][1], acc[i][2], acc[i][3]);
        }
    }
    __syncthreads();

    // reload: ws <- p1 (32 outs), xs <- shared
    for (int i = t; i < RR * DIMC; i += 384) {
        int o = i / DIMC, d = i % DIMC;
        ws[d * XST + o] = p1[(e * RR + o) * DIMC + d];
    }
    for (int i = t; i < 64 * (PXT / 4); i += 384) {
        int d = i / (PXT / 4), p4 = i % (PXT / 4);
        *(float4*)&xs[d * XST + p4 * 4] =
            *(const float4*)&shin[((size_t)b * DIMC + d) * HWPX + pbase + p4 * 4];
    }
    __syncthreads();

    // pass2 (first 256 threads): 8 out-groups x 32 px-groups; 4 outs x 4 px
    if (t < 256) {
        int og = t % 8, pg = t / 8;
        int o0 = og * 4, p0 = pg * 4;
        float acc[4][4];
#pragma unroll
        for (int i = 0; i < 4; i++)
#pragma unroll
            for (int j = 0; j < 4; j++) acc[i][j] = 0.f;
#pragma unroll 4
        for (int d = 0; d < DIMC; d++) {
            float4 w = *(const float4*)(ws + d * XST + o0);
            float4 xv = *(const float4*)(xs + d * XST + p0);
            float wv[4] = {w.x, w.y, w.z, w.w};
            float xr[4] = {xv.x, xv.y, xv.z, xv.w};
#pragma unroll
            for (int i = 0; i < 4; i++)
#pragma unroll
                for (int j = 0; j < 4; j++) acc[i][j] += wv[i] * xr[j];
        }
#pragma unroll
        for (int i = 0; i < 4; i++) {
            float4 r;
            float* pr = &r.x;
#pragma unroll
            for (int j = 0; j < 4; j++) {
                float s = acc[i][j];
                pr[j] = s / (1.f + expf(-s));
            }
            *(float4*)&d_gact[pair][o0 + i][pbase + p0] = r;
        }
    }
}

// ---------------- K4: depthwise conv, 32x32 tiles, 4 rows/thread ----------------
template <int R>
__device__ __forceinline__ void dwconv_tile(const float* __restrict__ src,
                                            const float* __restrict__ w,
                                            float* __restrict__ dst,
                                            int ty, int tx, float* tile) {
    const int KS = 2 * R + 1, TW = 32 + 2 * R;
    int t = threadIdx.x;
    for (int i = t; i < TW * TW; i += 256) {
        int iy = i / TW, ix = i % TW;
        int gy = ty + iy - R, gx = tx + ix - R;
        tile[i] = (gy >= 0 && gy < HH && gx >= 0 && gx < WW) ? src[gy * WW + gx] : 0.f;
    }
    float wr[KS * KS];
#pragma unroll
    for (int i = 0; i < KS * KS; i++) wr[i] = w[i];
    __syncthreads();
    int lx = t % 32, y0 = (t / 32) * 4;
    float acc[4] = {0.f, 0.f, 0.f, 0.f};
#pragma unroll
    for (int dx = 0; dx < KS; dx++) {
        float col[4 + 2 * R];
#pragma unroll
        for (int r = 0; r < 4 + 2 * R; r++) col[r] = tile[(y0 + r) * TW + lx + dx];
#pragma unroll
        for (int dy = 0; dy < KS; dy++)
#pragma unroll
            for (int oy = 0; oy < 4; oy++) acc[oy] += wr[dy * KS + dx] * col[oy + dy];
    }
#pragma unroll
    for (int oy = 0; oy < 4; oy++) dst[(ty + y0 + oy) * WW + tx + lx] = acc[oy];
}

__global__ __launch_bounds__(256) void k_dw(const float* __restrict__ q_dw,
                                            const float* __restrict__ kv_dw) {
    int pair = blockIdx.z;
    int b = pair / EE, e = pair % EE;
    if (d_gates[b][e] == 0.f) return;
    __shared__ float tile[38 * 38];
    int ch = blockIdx.y;
    int ty = (blockIdx.x >> 2) * 32, tx = (blockIdx.x & 3) * 32;
    if (ch < RR) {
        dwconv_tile<1>(&d_qpre[pair][ch][0], q_dw + (size_t)(e * RR + ch) * 9,
                       &d_qb[pair][ch][0], ty, tx, tile);
    } else {
        int c = ch - RR;
        float* dst = (c < RR) ? &d_kb[pair][c][0] : &d_vb[pair][c - RR][0];
        dwconv_tile<3>(&d_kvpre[pair][c][0], kv_dw + (size_t)(e * 2 * RR + c) * 49,
                       dst, ty, tx, tile);
    }
}

// ---------------- K5: 8x8 circular conv + LN + *v + po conv ----------------
__global__ __launch_bounds__(256) void k_patch(const float* __restrict__ ln_w,
                                               const float* __restrict__ ln_b,
                                               const float* __restrict__ po_w,
                                               const float* __restrict__ po_b) {
    int pair = blockIdx.y;
    int b = pair / EE, e = pair % EE;
    if (d_gates[b][e] == 0.f) return;
    int patch = blockIdx.x;
    int r0 = (patch / 16) * 8, c0 = (patch % 16) * 8;
    int t = threadIdx.x;

    __shared__ float sq[RR * 72];
    __shared__ float sk[RR * 72];
    __shared__ float sv[RR * 72];
    __shared__ float spw[RR * 33];
    __shared__ float spb[RR], slw[RR], slb[RR];

    {
        int c = t >> 3, pr = t & 7;
        size_t off = (size_t)(r0 + pr) * WW + c0;
        const float* qp = &d_qb[pair][c][off];
        const float* kp = &d_kb[pair][c][off];
        const float* vp = &d_vb[pair][c][off];
        *(float4*)&sq[c * 72 + pr * 8]     = *(const float4*)qp;
        *(float4*)&sq[c * 72 + pr * 8 + 4] = *(const float4*)(qp + 4);
        *(float4*)&sk[c * 72 + pr * 8]     = *(const float4*)kp;
        *(float4*)&sk[c * 72 + pr * 8 + 4] = *(const float4*)(kp + 4);
        *(float4*)&sv[c * 72 + pr * 8]     = *(const float4*)vp;
        *(float4*)&sv[c * 72 + pr * 8 + 4] = *(const float4*)(vp + 4);
    }
    for (int i = t; i < RR * RR; i += 256)
        spw[(i / RR) * 33 + (i % RR)] = po_w[(size_t)e * RR * RR + i];
    if (t < RR) {
        spb[t] = po_b[e * RR + t];
        slw[t] = ln_w[e * RR + t];
        slb[t] = ln_b[e * RR + t];
    }
    __syncthreads();

    // circular conv: thread (c, i) computes output row i (8 cols) of channel c
    int c = t >> 3, i = t & 7;
    float acc[8];
#pragma unroll
    for (int j = 0; j < 8; j++) acc[j] = 0.f;
#pragma unroll
    for (int u = 0; u < 8; u++) {
        float4 qa = *(const float4*)&sq[c * 72 + u * 8];
        float4 qb4 = *(const float4*)&sq[c * 72 + u * 8 + 4];
        float qv[8] = {qa.x, qa.y, qa.z, qa.w, qb4.x, qb4.y, qb4.z, qb4.w};
        int kr = (i - u) & 7;
        float4 ka = *(const float4*)&sk[c * 72 + kr * 8];
        float4 kb4 = *(const float4*)&sk[c * 72 + kr * 8 + 4];
        float kv[8] = {ka.x, ka.y, ka.z, ka.w, kb4.x, kb4.y, kb4.z, kb4.w};
#pragma unroll
        for (int j = 0; j < 8; j++)
#pragma unroll
            for (int v = 0; v < 8; v++) acc[j] += qv[v] * kv[(j - v) & 7];
    }
    __syncthreads();
    *(float4*)&sq[c * 72 + i * 8]     = make_float4(acc[0], acc[1], acc[2], acc[3]);
    *(float4*)&sq[c * 72 + i * 8 + 4] = make_float4(acc[4], acc[5], acc[6], acc[7]);
    __syncthreads();

    // LN over channels per pixel, * v  (result into sk)
    if (t < 64) {
        float mu = 0.f;
#pragma unroll
        for (int c2 = 0; c2 < RR; c2++) mu += sq[c2 * 72 + t];
        mu *= (1.f / RR);
        float var = 0.f;
#pragma unroll
        for (int c2 = 0; c2 < RR; c2++) {
            float d = sq[c2 * 72 + t] - mu;
            var += d * d;
        }
        var *= (1.f / RR);
        float rs = rsqrtf(var + 1e-5f);
#pragma unroll
        for (int c2 = 0; c2 < RR; c2++) {
            float val = (sq[c2 * 72 + t] - mu) * rs * slw[c2] + slb[c2];
            sk[c2 * 72 + t] = val * sv[c2 * 72 + t];
        }
    }
    __syncthreads();

    // po conv: thread (o, g) computes out row g (8 cols) for channel o
    int o = t >> 3, g = t & 7;
    float a2[8];
#pragma unroll
    for (int j = 0; j < 8; j++) a2[j] = 0.f;
#pragma unroll
    for (int c2 = 0; c2 < RR; c2++) {
        float w = spw[o * 33 + c2];
        float4 v0 = *(const float4*)&sk[c2 * 72 + g * 8];
        float4 v1 = *(const float4*)&sk[c2 * 72 + g * 8 + 4];
        a2[0] += w * v0.x; a2[1] += w * v0.y; a2[2] += w * v0.z; a2[3] += w * v0.w;
        a2[4] += w * v1.x; a2[5] += w * v1.y; a2[6] += w * v1.z; a2[7] += w * v1.w;
    }
    float bias = spb[o];
    float* dst = &d_attb[pair][o][(size_t)(r0 + g) * WW + c0];
    *(float4*)dst       = make_float4(a2[0] + bias, a2[1] + bias, a2[2] + bias, a2[3] + bias);
    *(float4*)(dst + 4) = make_float4(a2[4] + bias, a2[5] + bias, a2[6] + bias, a2[7] + bias);
}

// ---------------- K6: combine: out = gatesum*x + sum_e p2 @ (g*att*gact) ----------------
__global__ __launch_bounds__(256) void k_out(const float* __restrict__ x,
                                             const float* __restrict__ p2,
                                             float* __restrict__ out) {
    int b = blockIdx.y;
    __shared__ float avs[64 * 68];
    __shared__ float wsm[64 * 68];
    int e1 = d_topidx[b][0], e2 = d_topidx[b][1];
    float g1 = d_gates[b][e1], g2 = d_gates[b][e2];
    float gs = d_gatesum[b];
    int t = threadIdx.x;
    int pbase = blockIdx.x * 64;

    for (int idx = t; idx < 64 * 64; idx += 256) {
        int cc = idx / 64, o = idx % 64;
        int which = cc >> 5, c = cc & 31;
        int e = which ? e2 : e1;
        wsm[cc * 68 + o] = p2[((size_t)e * DIMC + o) * RR + c];
    }
    for (int idx = t; idx < 64 * 64; idx += 256) {
        int cc = idx / 64, p = idx % 64;
        int which = cc >> 5, c = cc & 31;
        int e = which ? e2 : e1;
        float g = which ? g2 : g1;
        int pr = b * EE + e;
        avs[cc * 68 + p] = g * d_attb[pr][c][pbase + p] * d_gact[pr][c][pbase + p];
    }
    __syncthreads();

    int og = t % 16, pg = t / 16;
    int o0 = og * 4, p0 = pg * 4;
    float acc[4][4];
#pragma unroll
    for (int i = 0; i < 4; i++)
#pragma unroll
        for (int j = 0; j < 4; j++) acc[i][j] = 0.f;
#pragma unroll 4
    for (int cc = 0; cc < 64; cc++) {
        float4 w = *(const float4*)&wsm[cc * 68 + o0];
        float4 a = *(const float4*)&avs[cc * 68 + p0];
        float wv[4] = {w.x, w.y, w.z, w.w};
        float av[4] = {a.x, a.y, a.z, a.w};
#pragma unroll
        for (int i = 0; i < 4; i++)
#pragma unroll
            for (int j = 0; j < 4; j++) acc[i][j] += wv[i] * av[j];
    }
#pragma unroll
    for (int i = 0; i < 4; i++) {
        size_t off = ((size_t)b * DIMC + o0 + i) * HWPX + pbase + p0;
        float4 xv = *(const float4*)&x[off];
        *(float4*)&out[off] = make_float4(acc[i][0] + gs * xv.x, acc[i][1] + gs * xv.y,
                                          acc[i][2] + gs * xv.z, acc[i][3] + gs * xv.w);
    }
}

// ---------------- launch ----------------
extern "C" void kernel_launch(void* const* d_in, const int* in_sizes, int n_in,
                              void* d_out, int out_size) {
    const float* x      = (const float*)d_in[0];
    const float* shin   = (const float*)d_in[1];
    const float* femb   = (const float*)d_in[2];
    const float* noise  = (const float*)d_in[3];
    const float* gate_w = (const float*)d_in[4];
    const float* fgw    = (const float*)d_in[5];
    const float* p0     = (const float*)d_in[6];
    const float* p1     = (const float*)d_in[7];
    const float* p2     = (const float*)d_in[8];
    const float* q_w    = (const float*)d_in[9];
    const float* q_dw   = (const float*)d_in[10];
    const float* kv_w   = (const float*)d_in[11];
    const float* kv_dw  = (const float*)d_in[12];
    const float* ln_w   = (const float*)d_in[13];
    const float* ln_b   = (const float*)d_in[14];
    const float* po_w   = (const float*)d_in[15];
    const float* po_b   = (const float*)d_in[16];
    float* out = (float*)d_out;

    static const int kPreSmem = 2 * 64 * XST * sizeof(float);
    cudaFuncSetAttribute(k_pre, cudaFuncAttributeMaxDynamicSharedMemorySize, kPreSmem);

    k_pool<<<BB * DIMC, 256>>>(x);
    k_gate<<<1, 32>>>(femb, noise, gate_w, fgw);
    k_compose<<<EE, 256>>>(p0, q_w, kv_w);
    k_pre<<<dim3(HWPX / PXT, NPAIR), 384, kPreSmem>>>(x, shin, p1);
    k_dw<<<dim3(16, 96, NPAIR), 256>>>(q_dw, kv_dw);
    k_patch<<<dim3(256, NPAIR), 256>>>(ln_w, ln_b, po_w, po_b);
    k_out<<<dim3(HWPX / 64, BB), 256>>>(x, p2, out);
}

// round 4
// speedup vs baseline: 1.9177x; 1.9177x over previous
#include <cuda_runtime.h>
#include <math.h>

#define BB 16
#define EE 4
#define DIMC 64
#define RR 32
#define HH 128
#define WW 128
#define HWPX (HH*WW)
#define FREQN 64
#define NPAIR (BB*EE)

typedef unsigned long long ull;

// ---- packed f32x2 helpers (sm_100+) ----
__device__ __forceinline__ ull pk2(float lo, float hi) {
    ull r;
    asm("mov.b64 %0, {%1, %2};" : "=l"(r) : "f"(lo), "f"(hi));
    return r;
}
__device__ __forceinline__ void fma2(ull& d, ull a, ull b) {
    asm("fma.rn.f32x2 %0, %1, %2, %0;" : "+l"(d) : "l"(a), "l"(b));
}
__device__ __forceinline__ float2 upk(ull v) {
    float lo, hi;
    asm("mov.b64 {%0, %1}, %2;" : "=f"(lo), "=f"(hi) : "l"(v));
    return make_float2(lo, hi);
}

// ---------------- scratch (device globals) ----------------
__device__ float d_pooled[BB][DIMC];
__device__ float d_gates[BB][EE];
__device__ float d_gatesum[BB];
__device__ int   d_topidx[BB][2];
__device__ float d_qc[EE][RR][DIMC];
__device__ float d_kvc[EE][2*RR][DIMC];
__device__ float d_qpre[NPAIR][RR][HWPX];
__device__ float d_kvpre[NPAIR][2*RR][HWPX];
__device__ float d_qb[NPAIR][RR][HWPX];
__device__ float d_kb[NPAIR][RR][HWPX];
__device__ float d_vb[NPAIR][RR][HWPX];
__device__ float d_gact[NPAIR][RR][HWPX];
__device__ float d_attb[NPAIR][RR][HWPX];

// ---------------- K0: pooled mean ----------------
__global__ void k_pool(const float* __restrict__ x) {
    int bc = blockIdx.x;
    const float* p = x + (size_t)bc * HWPX;
    float s = 0.f;
    for (int i = threadIdx.x; i < HWPX; i += 256) s += p[i];
    __shared__ float sm[256];
    sm[threadIdx.x] = s;
    __syncthreads();
    for (int o = 128; o > 0; o >>= 1) {
        if (threadIdx.x < o) sm[threadIdx.x] += sm[threadIdx.x + o];
        __syncthreads();
    }
    if (threadIdx.x == 0) d_pooled[bc / DIMC][bc % DIMC] = sm[0] * (1.f / (float)HWPX);
}

// ---------------- K1: gating ----------------
__global__ void k_gate(const float* __restrict__ freq_emb, const float* __restrict__ noise,
                       const float* __restrict__ gate_w, const float* __restrict__ fgw) {
    int b = threadIdx.x;
    if (b >= BB) return;
    float lg[EE];
    for (int e = 0; e < EE; e++) {
        float s = 0.f;
        for (int d = 0; d < DIMC; d++) s += d_pooled[b][d] * gate_w[e * DIMC + d];
        for (int f = 0; f < FREQN; f++) s += freq_emb[b * FREQN + f] * fgw[e * FREQN + f];
        lg[e] = s + noise[b * EE + e] * (1.0f / (float)EE);
    }
    float mx = lg[0];
    for (int e = 1; e < EE; e++) mx = fmaxf(mx, lg[e]);
    float se = 0.f, sc[EE];
    for (int e = 0; e < EE; e++) { sc[e] = expf(lg[e] - mx); se += sc[e]; }
    for (int e = 0; e < EE; e++) sc[e] /= se;
    int i1 = 0;
    for (int e = 1; e < EE; e++) if (sc[e] > sc[i1]) i1 = e;
    int i2 = -1;
    for (int e = 0; e < EE; e++) {
        if (e == i1) continue;
        if (i2 < 0 || sc[e] > sc[i2]) i2 = e;
    }
    for (int e = 0; e < EE; e++) d_gates[b][e] = (e == i1 || e == i2) ? sc[e] : 0.f;
    d_gatesum[b] = sc[i1] + sc[i2];
    d_topidx[b][0] = i1;
    d_topidx[b][1] = i2;
}

// ---------------- K2: compose q_w@p0, kv_w@p0 ----------------
__global__ void k_compose(const float* __restrict__ p0, const float* __restrict__ q_w,
                          const float* __restrict__ kv_w) {
    int e = blockIdx.x;
    __shared__ float sp0[RR][DIMC];
    for (int i = threadIdx.x; i < RR * DIMC; i += 256)
        sp0[i / DIMC][i % DIMC] = p0[e * RR * DIMC + i];
    __syncthreads();
    for (int i = threadIdx.x; i < RR * DIMC; i += 256) {
        int o = i / DIMC, d = i % DIMC;
        float s = 0.f;
        for (int c = 0; c < RR; c++) s += q_w[(e * RR + o) * RR + c] * sp0[c][d];
        d_qc[e][o][d] = s;
    }
    for (int i = threadIdx.x; i < 2 * RR * DIMC; i += 256) {
        int o = i / DIMC, d = i % DIMC;
        float s = 0.f;
        for (int c = 0; c < RR; c++) s += kv_w[(e * 2 * RR + o) * RR + c] * sp0[c][d];
        d_kvc[e][o][d] = s;
    }
}

// ---------------- K3: per-pixel matmuls, d-packed f32x2 ----------------
// lane = pixel (coalesced loads/stores), o warp-uniform (broadcast weight LDS).
__global__ __launch_bounds__(256) void k_pre(const float* __restrict__ x,
                                             const float* __restrict__ shin,
                                             const float* __restrict__ p1) {
    __shared__ float ws[96][DIMC];   // 24KB, natural [o][d] layout
    int pair = blockIdx.y;
    int b = pair / EE, e = pair % EE;
    if (d_gates[b][e] == 0.f) return;
    int t = threadIdx.x;
    int px = blockIdx.x * 256 + t;

    for (int i = t; i < 96 * DIMC; i += 256) {
        int o = i >> 6, d = i & 63;
        ws[o][d] = (o < RR) ? d_qc[e][o][d] : d_kvc[e][o - RR][d];
    }

    // pack x: xp[dp] = {x[2dp], x[2dp+1]}
    ull xp[32];
    {
        const float* xb = x + (size_t)b * DIMC * HWPX + px;
#pragma unroll
        for (int dp = 0; dp < 32; dp++)
            xp[dp] = pk2(xb[(size_t)(2 * dp) * HWPX], xb[(size_t)(2 * dp + 1) * HWPX]);
    }
    __syncthreads();

    // pass1: 96 outs
    for (int o = 0; o < 96; o++) {
        const ulonglong2* wrow = (const ulonglong2*)&ws[o][0];
        ull a0 = 0ull, a1 = 0ull;
#pragma unroll
        for (int i = 0; i < 16; i++) {
            ulonglong2 w = wrow[i];
            fma2(a0, xp[2 * i], w.x);
            fma2(a1, xp[2 * i + 1], w.y);
        }
        float2 r0 = upk(a0), r1 = upk(a1);
        float s = (r0.x + r0.y) + (r1.x + r1.y);
        float* dst = (o < RR) ? &d_qpre[pair][o][0] : &d_kvpre[pair][o - RR][0];
        dst[px] = s;
    }
    __syncthreads();

    // reload: ws <- p1, xp <- shared input
    for (int i = t; i < RR * DIMC; i += 256) {
        int o = i >> 6, d = i & 63;
        ws[o][d] = p1[(e * RR + o) * DIMC + d];
    }
    {
        const float* sb = shin + (size_t)b * DIMC * HWPX + px;
#pragma unroll
        for (int dp = 0; dp < 32; dp++)
            xp[dp] = pk2(sb[(size_t)(2 * dp) * HWPX], sb[(size_t)(2 * dp + 1) * HWPX]);
    }
    __syncthreads();

    // pass2: 32 outs, silu
    for (int o = 0; o < RR; o++) {
        const ulonglong2* wrow = (const ulonglong2*)&ws[o][0];
        ull a0 = 0ull, a1 = 0ull;
#pragma unroll
        for (int i = 0; i < 16; i++) {
            ulonglong2 w = wrow[i];
            fma2(a0, xp[2 * i], w.x);
            fma2(a1, xp[2 * i + 1], w.y);
        }
        float2 r0 = upk(a0), r1 = upk(a1);
        float s = (r0.x + r0.y) + (r1.x + r1.y);
        d_gact[pair][o][px] = s / (1.f + expf(-s));
    }
}

// ---------------- K4: depthwise conv, 32x32 tiles, 4 rows/thread ----------------
template <int R>
__device__ __forceinline__ void dwconv_tile(const float* __restrict__ src,
                                            const float* __restrict__ w,
                                            float* __restrict__ dst,
                                            int ty, int tx, float* tile) {
    const int KS = 2 * R + 1, TW = 32 + 2 * R;
    int t = threadIdx.x;
    for (int i = t; i < TW * TW; i += 256) {
        int iy = i / TW, ix = i % TW;
        int gy = ty + iy - R, gx = tx + ix - R;
        tile[i] = (gy >= 0 && gy < HH && gx >= 0 && gx < WW) ? src[gy * WW + gx] : 0.f;
    }
    float wr[KS * KS];
#pragma unroll
    for (int i = 0; i < KS * KS; i++) wr[i] = w[i];
    __syncthreads();
    int lx = t % 32, y0 = (t / 32) * 4;
    float acc[4] = {0.f, 0.f, 0.f, 0.f};
#pragma unroll
    for (int dx = 0; dx < KS; dx++) {
        float col[4 + 2 * R];
#pragma unroll
        for (int r = 0; r < 4 + 2 * R; r++) col[r] = tile[(y0 + r) * TW + lx + dx];
#pragma unroll
        for (int dy = 0; dy < KS; dy++)
#pragma unroll
            for (int oy = 0; oy < 4; oy++) acc[oy] += wr[dy * KS + dx] * col[oy + dy];
    }
#pragma unroll
    for (int oy = 0; oy < 4; oy++) dst[(ty + y0 + oy) * WW + tx + lx] = acc[oy];
}

__global__ __launch_bounds__(256) void k_dw(const float* __restrict__ q_dw,
                                            const float* __restrict__ kv_dw) {
    int pair = blockIdx.z;
    int b = pair / EE, e = pair % EE;
    if (d_gates[b][e] == 0.f) return;
    __shared__ float tile[38 * 38];
    int ch = blockIdx.y;
    int ty = (blockIdx.x >> 2) * 32, tx = (blockIdx.x & 3) * 32;
    if (ch < RR) {
        dwconv_tile<1>(&d_qpre[pair][ch][0], q_dw + (size_t)(e * RR + ch) * 9,
                       &d_qb[pair][ch][0], ty, tx, tile);
    } else {
        int c = ch - RR;
        float* dst = (c < RR) ? &d_kb[pair][c][0] : &d_vb[pair][c - RR][0];
        dwconv_tile<3>(&d_kvpre[pair][c][0], kv_dw + (size_t)(e * 2 * RR + c) * 49,
                       dst, ty, tx, tile);
    }
}

// ---------------- K5: 8x8 circular conv + LN + *v + po conv ----------------
__global__ __launch_bounds__(256) void k_patch(const float* __restrict__ ln_w,
                                               const float* __restrict__ ln_b,
                                               const float* __restrict__ po_w,
                                               const float* __restrict__ po_b) {
    int pair = blockIdx.y;
    int b = pair / EE, e = pair % EE;
    if (d_gates[b][e] == 0.f) return;
    int patch = blockIdx.x;
    int r0 = (patch / 16) * 8, c0 = (patch % 16) * 8;
    int t = threadIdx.x;

    __shared__ float sq[RR * 72];
    __shared__ float sk[RR * 72];
    __shared__ float sv[RR * 72];
    __shared__ float spw[RR * 33];
    __shared__ float spb[RR], slw[RR], slb[RR];

    {
        int c = t >> 3, pr = t & 7;
        size_t off = (size_t)(r0 + pr) * WW + c0;
        const float* qp = &d_qb[pair][c][off];
        const float* kp = &d_kb[pair][c][off];
        const float* vp = &d_vb[pair][c][off];
        *(float4*)&sq[c * 72 + pr * 8]     = *(const float4*)qp;
        *(float4*)&sq[c * 72 + pr * 8 + 4] = *(const float4*)(qp + 4);
        *(float4*)&sk[c * 72 + pr * 8]     = *(const float4*)kp;
        *(float4*)&sk[c * 72 + pr * 8 + 4] = *(const float4*)(kp + 4);
        *(float4*)&sv[c * 72 + pr * 8]     = *(const float4*)vp;
        *(float4*)&sv[c * 72 + pr * 8 + 4] = *(const float4*)(vp + 4);
    }
    for (int i = t; i < RR * RR; i += 256)
        spw[(i / RR) * 33 + (i % RR)] = po_w[(size_t)e * RR * RR + i];
    if (t < RR) {
        spb[t] = po_b[e * RR + t];
        slw[t] = ln_w[e * RR + t];
        slb[t] = ln_b[e * RR + t];
    }
    __syncthreads();

    // circular conv: thread (c, i) computes output row i (8 cols) of channel c
    int c = t >> 3, i = t & 7;
    float acc[8];
#pragma unroll
    for (int j = 0; j < 8; j++) acc[j] = 0.f;
#pragma unroll
    for (int u = 0; u < 8; u++) {
        float4 qa = *(const float4*)&sq[c * 72 + u * 8];
        float4 qb4 = *(const float4*)&sq[c * 72 + u * 8 + 4];
        float qv[8] = {qa.x, qa.y, qa.z, qa.w, qb4.x, qb4.y, qb4.z, qb4.w};
        int kr = (i - u) & 7;
        float4 ka = *(const float4*)&sk[c * 72 + kr * 8];
        float4 kb4 = *(const float4*)&sk[c * 72 + kr * 8 + 4];
        float kv[8] = {ka.x, ka.y, ka.z, ka.w, kb4.x, kb4.y, kb4.z, kb4.w};
#pragma unroll
        for (int j = 0; j < 8; j++)
#pragma unroll
            for (int v = 0; v < 8; v++) acc[j] += qv[v] * kv[(j - v) & 7];
    }
    __syncthreads();
    *(float4*)&sq[c * 72 + i * 8]     = make_float4(acc[0], acc[1], acc[2], acc[3]);
    *(float4*)&sq[c * 72 + i * 8 + 4] = make_float4(acc[4], acc[5], acc[6], acc[7]);
    __syncthreads();

    // LN over channels per pixel, * v  (result into sk)
    if (t < 64) {
        float mu = 0.f;
#pragma unroll
        for (int c2 = 0; c2 < RR; c2++) mu += sq[c2 * 72 + t];
        mu *= (1.f / RR);
        float var = 0.f;
#pragma unroll
        for (int c2 = 0; c2 < RR; c2++) {
            float d = sq[c2 * 72 + t] - mu;
            var += d * d;
        }
        var *= (1.f / RR);
        float rs = rsqrtf(var + 1e-5f);
#pragma unroll
        for (int c2 = 0; c2 < RR; c2++) {
            float val = (sq[c2 * 72 + t] - mu) * rs * slw[c2] + slb[c2];
            sk[c2 * 72 + t] = val * sv[c2 * 72 + t];
        }
    }
    __syncthreads();

    // po conv: thread (o, g) computes out row g (8 cols) for channel o
    int o = t >> 3, g = t & 7;
    float a2[8];
#pragma unroll
    for (int j = 0; j < 8; j++) a2[j] = 0.f;
#pragma unroll
    for (int c2 = 0; c2 < RR; c2++) {
        float w = spw[o * 33 + c2];
        float4 v0 = *(const float4*)&sk[c2 * 72 + g * 8];
        float4 v1 = *(const float4*)&sk[c2 * 72 + g * 8 + 4];
        a2[0] += w * v0.x; a2[1] += w * v0.y; a2[2] += w * v0.z; a2[3] += w * v0.w;
        a2[4] += w * v1.x; a2[5] += w * v1.y; a2[6] += w * v1.z; a2[7] += w * v1.w;
    }
    float bias = spb[o];
    float* dst = &d_attb[pair][o][(size_t)(r0 + g) * WW + c0];
    *(float4*)dst       = make_float4(a2[0] + bias, a2[1] + bias, a2[2] + bias, a2[3] + bias);
    *(float4*)(dst + 4) = make_float4(a2[4] + bias, a2[5] + bias, a2[6] + bias, a2[7] + bias);
}

// ---------------- K6: combine, cc-packed f32x2, lane = pixel ----------------
__global__ __launch_bounds__(256) void k_out(const float* __restrict__ x,
                                             const float* __restrict__ p2,
                                             float* __restrict__ out) {
    __shared__ float ws[DIMC][64];   // [o][cc] 16KB; cc = expert-slot*32 + c
    int b = blockIdx.y;
    int e1 = d_topidx[b][0], e2 = d_topidx[b][1];
    float g1 = d_gates[b][e1], g2 = d_gates[b][e2];
    float gs = d_gatesum[b];
    int t = threadIdx.x;
    int px = blockIdx.x * 256 + t;

    for (int i = t; i < DIMC * 64; i += 256) {
        int o = i >> 6, cc = i & 63;
        int e = (cc < RR) ? e1 : e2;
        ws[o][cc] = p2[((size_t)e * DIMC + o) * RR + (cc & 31)];
    }

    // gated activations, packed over cc
    ull av[32];
    {
        int pr1 = b * EE + e1, pr2 = b * EE + e2;
#pragma unroll
        for (int i = 0; i < 16; i++) {
            float f0 = g1 * d_attb[pr1][2 * i][px] * d_gact[pr1][2 * i][px];
            float f1 = g1 * d_attb[pr1][2 * i + 1][px] * d_gact[pr1][2 * i + 1][px];
            av[i] = pk2(f0, f1);
        }
#pragma unroll
        for (int i = 0; i < 16; i++) {
            float f0 = g2 * d_attb[pr2][2 * i][px] * d_gact[pr2][2 * i][px];
            float f1 = g2 * d_attb[pr2][2 * i + 1][px] * d_gact[pr2][2 * i + 1][px];
            av[16 + i] = pk2(f0, f1);
        }
    }
    __syncthreads();

    const float* xb = x + (size_t)b * DIMC * HWPX + px;
    float* ob = out + (size_t)b * DIMC * HWPX + px;
    for (int o = 0; o < DIMC; o++) {
        const ulonglong2* wrow = (const ulonglong2*)&ws[o][0];
        ull a0 = 0ull, a1 = 0ull;
#pragma unroll
        for (int i = 0; i < 16; i++) {
            ulonglong2 w = wrow[i];
            fma2(a0, av[2 * i], w.x);
            fma2(a1, av[2 * i + 1], w.y);
        }
        float2 r0 = upk(a0), r1 = upk(a1);
        float s = (r0.x + r0.y) + (r1.x + r1.y);
        ob[(size_t)o * HWPX] = s + gs * xb[(size_t)o * HWPX];
    }
}

// ---------------- launch ----------------
extern "C" void kernel_launch(void* const* d_in, const int* in_sizes, int n_in,
                              void* d_out, int out_size) {
    const float* x      = (const float*)d_in[0];
    const float* shin   = (const float*)d_in[1];
    const float* femb   = (const float*)d_in[2];
    const float* noise  = (const float*)d_in[3];
    const float* gate_w = (const float*)d_in[4];
    const float* fgw    = (const float*)d_in[5];
    const float* p0     = (const float*)d_in[6];
    const float* p1     = (const float*)d_in[7];
    const float* p2     = (const float*)d_in[8];
    const float* q_w    = (const float*)d_in[9];
    const float* q_dw   = (const float*)d_in[10];
    const float* kv_w   = (const float*)d_in[11];
    const float* kv_dw  = (const float*)d_in[12];
    const float* ln_w   = (const float*)d_in[13];
    const float* ln_b   = (const float*)d_in[14];
    const float* po_w   = (const float*)d_in[15];
    const float* po_b   = (const float*)d_in[16];
    float* out = (float*)d_out;

    k_pool<<<BB * DIMC, 256>>>(x);
    k_gate<<<1, 32>>>(femb, noise, gate_w, fgw);
    k_compose<<<EE, 256>>>(p0, q_w, kv_w);
    k_pre<<<dim3(HWPX / 256, NPAIR), 256>>>(x, shin, p1);
    k_dw<<<dim3(16, 96, NPAIR), 256>>>(q_dw, kv_dw);
    k_patch<<<dim3(256, NPAIR), 256>>>(ln_w, ln_b, po_w, po_b);
    k_out<<<dim3(HWPX / 256, BB), 256>>>(x, p2, out);
}